// round 1
// baseline (speedup 1.0000x reference)
#include <cuda_runtime.h>
#include <math_constants.h>

// Output layout (float32, out_size = 6*E):
//   [0      , 3E) : vec, row-major [E,3]
//   [3E     , 4E) : distances
//   [4E     , 5E) : switch
//   [5E     , 6E) : edge_mask as 0.0/1.0
__global__ void __launch_bounds__(256) graph_edge_kernel(
    const float* __restrict__ coords,   // [N,3]
    const int*   __restrict__ esrc,     // [E]
    const int*   __restrict__ edst,     // [E]
    const float* __restrict__ shifts,   // [E,3]
    const float* __restrict__ cells,    // [1,3,3] row-major
    float*       __restrict__ out,
    int E)
{
    int i = blockIdx.x * blockDim.x + threadIdx.x;
    if (i >= E) return;

    // cells broadcast (uniform across all threads; L1-resident)
    const float c00 = __ldg(cells + 0), c01 = __ldg(cells + 1), c02 = __ldg(cells + 2);
    const float c10 = __ldg(cells + 3), c11 = __ldg(cells + 4), c12 = __ldg(cells + 5);
    const float c20 = __ldg(cells + 6), c21 = __ldg(cells + 7), c22 = __ldg(cells + 8);

    const int s = __ldg(esrc + i);
    const int d = __ldg(edst + i);

    // gather node coordinates (coord table = 1.2 MB -> L2 resident)
    const float dx = __ldg(coords + 3 * d + 0) - __ldg(coords + 3 * s + 0);
    const float dy = __ldg(coords + 3 * d + 1) - __ldg(coords + 3 * s + 1);
    const float dz = __ldg(coords + 3 * d + 2) - __ldg(coords + 3 * s + 2);

    const float sx = __ldg(shifts + 3 * i + 0);
    const float sy = __ldg(shifts + 3 * i + 1);
    const float sz = __ldg(shifts + 3 * i + 2);

    // vec = (coords[dst]-coords[src]) + shifts @ cells[0]
    // (row-vector times matrix: out_j = sum_k shift_k * cells[k][j])
    const float vx = dx + sx * c00 + sy * c10 + sz * c20;
    const float vy = dy + sx * c01 + sy * c11 + sz * c21;
    const float vz = dz + sx * c02 + sy * c12 + sz * c22;

    const float dist = sqrtf(vx * vx + vy * vy + vz * vz);
    const bool  m    = dist < 5.0f;
    const float sw   = m ? (0.5f * cosf(dist * (CUDART_PI_F / 5.0f)) + 0.5f) : 0.0f;

    out[3 * i + 0] = vx;
    out[3 * i + 1] = vy;
    out[3 * i + 2] = vz;

    const long long E64 = E;
    out[3 * E64 + i] = dist;
    out[4 * E64 + i] = sw;
    out[5 * E64 + i] = m ? 1.0f : 0.0f;
}

extern "C" void kernel_launch(void* const* d_in, const int* in_sizes, int n_in,
                              void* d_out, int out_size)
{
    const float* coords = (const float*)d_in[0];
    const int*   esrc   = (const int*)  d_in[1];
    const int*   edst   = (const int*)  d_in[2];
    const float* shifts = (const float*)d_in[3];
    const float* cells  = (const float*)d_in[4];
    float*       out    = (float*)d_out;

    const int E = in_sizes[1];
    const int threads = 256;
    const int blocks  = (E + threads - 1) / threads;
    graph_edge_kernel<<<blocks, threads>>>(coords, esrc, edst, shifts, cells, out, E);
}

// round 3
// speedup vs baseline: 1.0799x; 1.0799x over previous
#include <cuda_runtime.h>
#include <math_constants.h>

// Scratch: coords padded to float4 for single-LDG.128 gathers (16B aligned by definition).
__device__ float4 g_coords4[131072];

__global__ void __launch_bounds__(256) pad_coords_kernel(
    const float* __restrict__ coords, int n)
{
    int i = blockIdx.x * blockDim.x + threadIdx.x;
    if (i < n) {
        g_coords4[i] = make_float4(coords[3 * i + 0],
                                   coords[3 * i + 1],
                                   coords[3 * i + 2], 0.0f);
    }
}

// Output layout (float32, out_size = 6*E):
//   [0 , 3E) : vec [E,3]   [3E,4E) : dist   [4E,5E) : switch   [5E,6E) : mask
__global__ void __launch_bounds__(256) graph_edge_kernel(
    const int*   __restrict__ esrc,     // [E]
    const int*   __restrict__ edst,     // [E]
    const float* __restrict__ shifts,   // [E,3]
    const float* __restrict__ cells,    // [1,3,3]
    float*       __restrict__ out,
    int E)
{
    __shared__ float s_cells[9];
    __shared__ float stage[256 * 3];    // reused: shifts in, vec out

    const int t = threadIdx.x;
    const long long base = (long long)blockIdx.x * 256;
    const long long i = base + t;
    const bool active = (i < (long long)E);
    const int nf = active ? min(256 * 3, (int)(((long long)E - base) * 3)) : 0;

    if (t < 9) s_cells[t] = __ldg(cells + t);

    // ---- stage shifts: 3 coalesced scalar loads per thread (alignment-safe,
    //      same wavefront count as float4: 128B per warp per instruction) ----
    #pragma unroll
    for (int k = t; k < 256 * 3; k += 256) {
        if (k < nf) stage[k] = __ldg(shifts + base * 3 + k);
    }
    __syncthreads();

    float vx = 0.f, vy = 0.f, vz = 0.f, dist = 0.f, sw = 0.f, mf = 0.f;
    if (active) {
        const int s = __ldg(esrc + i);
        const int d = __ldg(edst + i);

        const float4 cd = g_coords4[d];   // single LDG.128 gather
        const float4 cs = g_coords4[s];

        // stride-3 shared reads: gcd(3,32)=1 -> conflict-free
        const float sx = stage[3 * t + 0];
        const float sy = stage[3 * t + 1];
        const float sz = stage[3 * t + 2];

        vx = (cd.x - cs.x) + sx * s_cells[0] + sy * s_cells[3] + sz * s_cells[6];
        vy = (cd.y - cs.y) + sx * s_cells[1] + sy * s_cells[4] + sz * s_cells[7];
        vz = (cd.z - cs.z) + sx * s_cells[2] + sy * s_cells[5] + sz * s_cells[8];

        dist = sqrtf(vx * vx + vy * vy + vz * vz);
        const bool m = dist < 5.0f;
        // arg in [0, pi): __cosf abs error ~1e-6 << 1e-3 tolerance
        sw = m ? (0.5f * __cosf(dist * (CUDART_PI_F / 5.0f)) + 0.5f) : 0.0f;
        mf = m ? 1.0f : 0.0f;
    }

    // ---- stage vec in shared, then 3 coalesced scalar stores per thread ----
    __syncthreads();
    if (active) {
        stage[3 * t + 0] = vx;
        stage[3 * t + 1] = vy;
        stage[3 * t + 2] = vz;
    }
    __syncthreads();

    #pragma unroll
    for (int k = t; k < 256 * 3; k += 256) {
        if (k < nf) out[base * 3 + k] = stage[k];
    }

    if (active) {
        const long long E64 = E;
        out[3 * E64 + i] = dist;   // coalesced
        out[4 * E64 + i] = sw;
        out[5 * E64 + i] = mf;
    }
}

extern "C" void kernel_launch(void* const* d_in, const int* in_sizes, int n_in,
                              void* d_out, int out_size)
{
    const float* coords = (const float*)d_in[0];
    const int*   esrc   = (const int*)  d_in[1];
    const int*   edst   = (const int*)  d_in[2];
    const float* shifts = (const float*)d_in[3];
    const float* cells  = (const float*)d_in[4];
    float*       out    = (float*)d_out;

    const int N = in_sizes[0] / 3;
    const int E = in_sizes[1];

    pad_coords_kernel<<<(N + 255) / 256, 256>>>(coords, N);

    const int threads = 256;
    const int blocks  = (E + threads - 1) / threads;
    graph_edge_kernel<<<blocks, threads>>>(esrc, edst, shifts, cells, out, E);
}

// round 5
// speedup vs baseline: 1.2369x; 1.1454x over previous
#include <cuda_runtime.h>
#include <math_constants.h>

// Coords padded to float4 -> single LDG.128 per gather (16B aligned by definition).
__device__ float4 g_coords4[131072];

__global__ void __launch_bounds__(256) pad_coords_kernel(
    const float* __restrict__ coords, int n)
{
    int i = blockIdx.x * blockDim.x + threadIdx.x;
    if (i < n) {
        g_coords4[i] = make_float4(coords[3 * i + 0],
                                   coords[3 * i + 1],
                                   coords[3 * i + 2], 0.0f);
    }
    // PDL: our writes are fenced; let the dependent kernel proceed.
    __threadfence();
    cudaTriggerProgrammaticLaunchCompletion();
}

#define EPB 512   // edges per block (2 per thread, 256 threads)

// Output layout (float32, out_size = 6*E):
//   [0 , 3E) : vec [E,3]   [3E,4E) : dist   [4E,5E) : switch   [5E,6E) : mask
__global__ void __launch_bounds__(256) graph_edge_kernel(
    const int*   __restrict__ esrc,
    const int*   __restrict__ edst,
    const float* __restrict__ shifts,
    const float* __restrict__ cells,
    float*       __restrict__ out,
    int E)
{
    __shared__ float s_cells[9];
    __shared__ float stage[EPB * 3];     // vec staging for coalesced store

    const int t = threadIdx.x;
    const long long base = (long long)blockIdx.x * EPB;
    const long long i0 = base + t;
    const long long i1 = base + t + 256;
    const bool a0 = (i0 < (long long)E);
    const bool a1 = (i1 < (long long)E);

    if (t < 9) s_cells[t] = __ldg(cells + t);

    // ---- issue ALL independent streaming loads up front (deep MLP) ----
    int s0 = 0, d0 = 0, s1 = 0, d1 = 0;
    float sx0 = 0.f, sy0 = 0.f, sz0 = 0.f, sx1 = 0.f, sy1 = 0.f, sz1 = 0.f;
    if (a0) {
        s0  = __ldg(esrc + i0);
        d0  = __ldg(edst + i0);
        sx0 = __ldg(shifts + 3 * i0 + 0);
        sy0 = __ldg(shifts + 3 * i0 + 1);
        sz0 = __ldg(shifts + 3 * i0 + 2);
    }
    if (a1) {
        s1  = __ldg(esrc + i1);
        d1  = __ldg(edst + i1);
        sx1 = __ldg(shifts + 3 * i1 + 0);
        sy1 = __ldg(shifts + 3 * i1 + 1);
        sz1 = __ldg(shifts + 3 * i1 + 2);
    }

    // Barrier for s_cells visibility (R4 bug: this was missing). Placed here so
    // its cost hides under the in-flight streaming loads above.
    __syncthreads();

    // PDL: gathers read pad_coords_kernel's output — wait for it here.
    cudaGridDependencySynchronize();

    float4 cs0 = make_float4(0.f, 0.f, 0.f, 0.f), cd0 = cs0, cs1 = cs0, cd1 = cs0;
    if (a0) { cd0 = g_coords4[d0]; cs0 = g_coords4[s0]; }
    if (a1) { cd1 = g_coords4[d1]; cs1 = g_coords4[s1]; }

    const float c00 = s_cells[0], c01 = s_cells[1], c02 = s_cells[2];
    const float c10 = s_cells[3], c11 = s_cells[4], c12 = s_cells[5];
    const float c20 = s_cells[6], c21 = s_cells[7], c22 = s_cells[8];

    float dist0 = 0.f, sw0 = 0.f, mf0 = 0.f;
    float dist1 = 0.f, sw1 = 0.f, mf1 = 0.f;

    if (a0) {
        const float vx = (cd0.x - cs0.x) + sx0 * c00 + sy0 * c10 + sz0 * c20;
        const float vy = (cd0.y - cs0.y) + sx0 * c01 + sy0 * c11 + sz0 * c21;
        const float vz = (cd0.z - cs0.z) + sx0 * c02 + sy0 * c12 + sz0 * c22;
        stage[3 * t + 0] = vx;
        stage[3 * t + 1] = vy;
        stage[3 * t + 2] = vz;
        dist0 = sqrtf(vx * vx + vy * vy + vz * vz);
        const bool m = dist0 < 5.0f;
        sw0 = m ? (0.5f * __cosf(dist0 * (CUDART_PI_F / 5.0f)) + 0.5f) : 0.0f;
        mf0 = m ? 1.0f : 0.0f;
    }
    if (a1) {
        const int u = t + 256;
        const float vx = (cd1.x - cs1.x) + sx1 * c00 + sy1 * c10 + sz1 * c20;
        const float vy = (cd1.y - cs1.y) + sx1 * c01 + sy1 * c11 + sz1 * c21;
        const float vz = (cd1.z - cs1.z) + sx1 * c02 + sy1 * c12 + sz1 * c22;
        stage[3 * u + 0] = vx;
        stage[3 * u + 1] = vy;
        stage[3 * u + 2] = vz;
        dist1 = sqrtf(vx * vx + vy * vy + vz * vz);
        const bool m = dist1 < 5.0f;
        sw1 = m ? (0.5f * __cosf(dist1 * (CUDART_PI_F / 5.0f)) + 0.5f) : 0.0f;
        mf1 = m ? 1.0f : 0.0f;
    }

    __syncthreads();

    // ---- coalesced scalar stores of staged vec (alignment-safe) ----
    const int nf = (int)(min((long long)EPB, (long long)E - base) * 3);
    #pragma unroll
    for (int k = t; k < EPB * 3; k += 256) {
        if (k < nf) out[base * 3 + k] = stage[k];
    }

    const long long E64 = E;
    if (a0) {
        out[3 * E64 + i0] = dist0;
        out[4 * E64 + i0] = sw0;
        out[5 * E64 + i0] = mf0;
    }
    if (a1) {
        out[3 * E64 + i1] = dist1;
        out[4 * E64 + i1] = sw1;
        out[5 * E64 + i1] = mf1;
    }
}

extern "C" void kernel_launch(void* const* d_in, const int* in_sizes, int n_in,
                              void* d_out, int out_size)
{
    const float* coords = (const float*)d_in[0];
    const int*   esrc   = (const int*)  d_in[1];
    const int*   edst   = (const int*)  d_in[2];
    const float* shifts = (const float*)d_in[3];
    const float* cells  = (const float*)d_in[4];
    float*       out    = (float*)d_out;

    const int N = in_sizes[0] / 3;
    const int E = in_sizes[1];

    pad_coords_kernel<<<(N + 255) / 256, 256>>>(coords, N);

    const int blocks = (E + EPB - 1) / EPB;

    // PDL launch of the main kernel; fall back to a plain launch on error.
    cudaLaunchConfig_t cfg = {};
    cfg.gridDim  = dim3(blocks, 1, 1);
    cfg.blockDim = dim3(256, 1, 1);
    cfg.dynamicSmemBytes = 0;
    cfg.stream = 0;
    cudaLaunchAttribute attr[1];
    attr[0].id = cudaLaunchAttributeProgrammaticStreamSerialization;
    attr[0].val.programmaticStreamSerializationAllowed = 1;
    cfg.attrs = attr;
    cfg.numAttrs = 1;

    cudaError_t err = cudaLaunchKernelEx(&cfg, graph_edge_kernel,
                                         esrc, edst, shifts, cells, out, E);
    if (err != cudaSuccess) {
        (void)cudaGetLastError();  // clear
        graph_edge_kernel<<<blocks, 256>>>(esrc, edst, shifts, cells, out, E);
    }
}